// round 8
// baseline (speedup 1.0000x reference)
#include <cuda_runtime.h>
#include <cuda_bf16.h>

#define D 512
#define MAXC 512
#define MAXN 32768
#define NBLK 64

// Scratch (__device__ globals per allocation-free rule)
__device__ int g_part[NBLK * MAXC];   // per-block class histograms [b][c]
__device__ int g_offsets[MAXC + 1];   // class offsets into g_idx
__device__ int g_idx[MAXN];           // row offsets (i*D), grouped by class

// Grid barrier state. Self-restoring: g_barcnt reset by last arriver each
// barrier; g_sense flips per barrier and the kernel executes an EVEN number
// of barriers, so both return to 0 before every launch (graph-replay safe).
__device__ unsigned g_barcnt = 0;
__device__ volatile int g_sense = 0;

// Sense-reversing spin barrier across all NBLK resident blocks.
__device__ __forceinline__ void grid_barrier(int* s_sense) {
    __syncthreads();
    if (threadIdx.x == 0) {
        int target = 1 - *s_sense;
        *s_sense = target;
        __threadfence();  // make this block's prior stores visible
        unsigned prev = atomicAdd(&g_barcnt, 1u);
        if (prev == NBLK - 1) {
            g_barcnt = 0;          // safe: all blocks have arrived
            __threadfence();
            g_sense = target;      // release spinners
        } else {
            while (g_sense != target) {}
        }
        __threadfence();  // acquire: order spin-exit before subsequent loads
    }
    __syncthreads();
}

// ---------------------------------------------------------------------------
// Fused prep: histogram -> grid barrier -> scan -> scatter -> grid barrier.
// Grid MUST be exactly NBLK blocks of MAXC threads (thread t owns class t).
__global__ void prep_kernel(const int* __restrict__ targets, int N,
                            float* __restrict__ out) {
    __shared__ int sh[MAXC];
    __shared__ int scur[MAXC];
    __shared__ int s_sense;
    int t = threadIdx.x;   // blockDim.x == MAXC
    int b = blockIdx.x;

    if (t == 0) s_sense = 0;
    sh[t] = 0;
    __syncthreads();

    // Phase 1: per-block histogram (smem atomics only)
    for (int i = b * MAXC + t; i < N; i += NBLK * MAXC)
        atomicAdd(&sh[targets[i]], 1);
    __syncthreads();
    g_part[b * MAXC + t] = sh[t];

    grid_barrier(&s_sense);   // all per-block histograms visible

    // Phase 2: cross-block prefix for class t + class-offset scan
    int run = 0, total = 0;
    #pragma unroll
    for (int bb = 0; bb < NBLK; bb++) {
        int v = g_part[bb * MAXC + t];   // coalesced across t, L2-hot
        if (bb < b) run += v;
        total += v;
    }
    __syncthreads();          // sh reuse
    sh[t] = total;
    __syncthreads();
    for (int off = 1; off < MAXC; off <<= 1) {
        int v = sh[t];
        int add = (t >= off) ? sh[t - off] : 0;
        __syncthreads();
        sh[t] = v + add;
        __syncthreads();
    }
    int excl = (t == 0) ? 0 : sh[t - 1];
    scur[t] = excl + run;
    if (b == 0) {
        g_offsets[t] = excl;
        if (t == MAXC - 1) g_offsets[MAXC] = sh[MAXC - 1];
        if (t == 0) out[0] = 0.0f;
    }
    __syncthreads();

    // Phase 3: scatter via smem cursors (identical mapping to phase 1)
    for (int i = b * MAXC + t; i < N; i += NBLK * MAXC) {
        int c = targets[i];
        int p = atomicAdd(&scur[c], 1);
        g_idx[p] = i * D;  // pre-scaled row offset
    }

    grid_barrier(&s_sense);   // even barrier count -> g_sense restored to 0
}

__device__ __forceinline__ void f4acc(float4& a, const float4 v) {
    a.x += v.x; a.y += v.y; a.z += v.z; a.w += v.w;
}

// ---------------------------------------------------------------------------
// Gather-reduce + smooth-L1 epilogue. gridDim = (C, 2), blockDim = 256.
// launch_bounds(256,6): 6*148 = 888 >= 790 CTAs -> single resident wave,
// while allowing 42 regs for 4 independent float4 accumulator chains.
__global__ __launch_bounds__(256, 6)
void reduce_kernel(const float* __restrict__ m1,
                   const float* __restrict__ m2,
                   const float* __restrict__ centers,
                   float* __restrict__ out,
                   float inv_nd) {
    int c = blockIdx.x;
    const float* __restrict__ data = blockIdx.y ? m2 : m1;
    int beg = g_offsets[c];
    int end = g_offsets[c + 1];
    int cnt = end - beg;
    if (cnt == 0) return;  // empty classes contribute 0 (never gathered in ref)

    __shared__ int   sidx[1024];
    __shared__ float swarp[8];

    int tid = threadIdx.x;
    int q = tid & 1;
    int g = tid >> 1;

    float4 a0 = make_float4(0.f, 0.f, 0.f, 0.f);
    float4 a1 = make_float4(0.f, 0.f, 0.f, 0.f);
    float4 a2 = make_float4(0.f, 0.f, 0.f, 0.f);
    float4 a3 = make_float4(0.f, 0.f, 0.f, 0.f);

    for (int cs = beg; cs < end; cs += 1024) {
        int m = min(1024, end - cs);
        __syncthreads();
        for (int j = tid; j < m; j += blockDim.x)
            sidx[j] = g_idx[cs + j];
        __syncthreads();

        // 2 row-phases across q; 4 independent LDG.128 chains per thread
        int j = q;
        for (; j + 6 < m; j += 8) {
            f4acc(a0, __ldg((const float4*)(data + sidx[j])     + g));
            f4acc(a1, __ldg((const float4*)(data + sidx[j + 2]) + g));
            f4acc(a2, __ldg((const float4*)(data + sidx[j + 4]) + g));
            f4acc(a3, __ldg((const float4*)(data + sidx[j + 6]) + g));
        }
        for (; j < m; j += 2)
            f4acc(a0, __ldg((const float4*)(data + sidx[j]) + g));
    }
    f4acc(a0, a1);
    f4acc(a2, a3);
    f4acc(a0, a2);

    // Combine the 2 row-phases (adjacent lanes share g)
    a0.x += __shfl_xor_sync(0xffffffff, a0.x, 1);
    a0.y += __shfl_xor_sync(0xffffffff, a0.y, 1);
    a0.z += __shfl_xor_sync(0xffffffff, a0.z, 1);
    a0.w += __shfl_xor_sync(0xffffffff, a0.w, 1);

    float v = 0.0f;
    if (q == 0) {
        float inv_cnt = 1.0f / (float)cnt;
        float4 ctr = __ldg((const float4*)(centers + c * D) + g);
        float dx = fabsf(a0.x * inv_cnt - ctr.x);
        float dy = fabsf(a0.y * inv_cnt - ctr.y);
        float dz = fabsf(a0.z * inv_cnt - ctr.z);
        float dw = fabsf(a0.w * inv_cnt - ctr.w);
        float l = ((dx < 1.f) ? 0.5f * dx * dx : dx - 0.5f)
                + ((dy < 1.f) ? 0.5f * dy * dy : dy - 0.5f)
                + ((dz < 1.f) ? 0.5f * dz * dz : dz - 0.5f)
                + ((dw < 1.f) ? 0.5f * dw * dw : dw - 0.5f);
        v = l * (float)cnt;
    }

    // Block reduction (256 threads -> 8 warps -> scalar)
    #pragma unroll
    for (int o = 16; o; o >>= 1) v += __shfl_xor_sync(0xffffffff, v, o);
    if ((tid & 31) == 0) swarp[tid >> 5] = v;
    __syncthreads();
    if (tid < 32) {
        float w = (tid < 8) ? swarp[tid] : 0.0f;
        #pragma unroll
        for (int o = 4; o; o >>= 1) w += __shfl_xor_sync(0xffffffff, w, o);
        if (tid == 0) atomicAdd(out, w * inv_nd);
    }
}

// ---------------------------------------------------------------------------
extern "C" void kernel_launch(void* const* d_in, const int* in_sizes, int n_in,
                              void* d_out, int out_size) {
    const float* m1      = (const float*)d_in[0];  // modal1_inputs [N, 512]
    const float* m2      = (const float*)d_in[1];  // modal2_inputs [N, 512]
    const float* centers = (const float*)d_in[2];  // centers [C, 512]
    const int*   targets = (const int*)d_in[3];    // targets [N]

    int N = in_sizes[3];
    int C = in_sizes[2] / D;
    float* out = (float*)d_out;
    float inv_nd = 1.0f / ((float)N * (float)D);

    prep_kernel<<<NBLK, MAXC>>>(targets, N, out);
    dim3 grid(C, 2);
    reduce_kernel<<<grid, 256>>>(m1, m2, centers, out, inv_nd);
}